// round 2
// baseline (speedup 1.0000x reference)
#include <cuda_runtime.h>

#define N_NODES 50000
#define R_REL 51
#define F_DIM 32
#define E_DIM 32
#define C_DIM 16
#define B_BASES 30

// Scratch (no device allocation allowed in kernel_launch)
__device__ float g_w1[R_REL * F_DIM * E_DIM];   // [r][f][e]  208 KB
__device__ float g_w2[R_REL * E_DIM * C_DIM];   // [r][h][c]  104 KB
__device__ float g_h1[N_NODES * E_DIM];         // 6.4 MB

// ---------------------------------------------------------------------------
// Precompute per-relation weight matrices from the basis decomposition.
// w1[r,f,e] = sum_b comps1[r,b] * bases1[b,f,e]   (and same for w2)
// ---------------------------------------------------------------------------
__global__ void compute_w_kernel(const float* __restrict__ comps1,
                                 const float* __restrict__ bases1,
                                 const float* __restrict__ comps2,
                                 const float* __restrict__ bases2) {
    int idx = blockIdx.x * blockDim.x + threadIdx.x;
    const int total1 = R_REL * F_DIM * E_DIM;   // 52224
    const int total2 = R_REL * E_DIM * C_DIM;   // 26112
    if (idx < total1) {
        int r  = idx / (F_DIM * E_DIM);
        int fe = idx - r * (F_DIM * E_DIM);
        float acc = 0.f;
#pragma unroll
        for (int b = 0; b < B_BASES; b++)
            acc = fmaf(comps1[r * B_BASES + b], bases1[b * (F_DIM * E_DIM) + fe], acc);
        g_w1[idx] = acc;
    }
    if (idx < total2) {
        int r  = idx / (E_DIM * C_DIM);
        int hc = idx - r * (E_DIM * C_DIM);
        float acc = 0.f;
#pragma unroll
        for (int b = 0; b < B_BASES; b++)
            acc = fmaf(comps2[r * B_BASES + b], bases2[b * (E_DIM * C_DIM) + hc], acc);
        g_w2[idx] = acc;
    }
}

__global__ void init_h1_kernel() {
    int idx = blockIdx.x * blockDim.x + threadIdx.x;
    if (idx < N_NODES * E_DIM) g_h1[idx] = 0.f;
}

// ---------------------------------------------------------------------------
// Layer 1 fused edge kernel: one warp per edge (grid-stride).
// lane = output e.  h1[n,e] += v * sum_f x[m,f] * w1[r,f,e]
// ---------------------------------------------------------------------------
__global__ void layer1_kernel(const int* __restrict__ rows,
                              const int* __restrict__ cols,
                              const float* __restrict__ vals,
                              const float* __restrict__ x,
                              int nnz) {
    const int lane   = threadIdx.x & 31;
    const int warp   = (blockIdx.x * blockDim.x + threadIdx.x) >> 5;
    const int nwarps = (gridDim.x * blockDim.x) >> 5;
    for (int e = warp; e < nnz; e += nwarps) {
        unsigned row = (unsigned)rows[e];
        unsigned m   = (unsigned)cols[e];
        float    v   = vals[e];
        unsigned r   = row / N_NODES;          // compiler emits magic-mul
        unsigned n   = row - r * N_NODES;
        float xv = x[m * F_DIM + lane];        // coalesced 128B gather
        const float* w = g_w1 + r * (F_DIM * E_DIM);
        float acc = 0.f;
#pragma unroll
        for (int f = 0; f < F_DIM; f++) {
            float xf = __shfl_sync(0xffffffffu, xv, f);
            acc = fmaf(xf, __ldg(w + f * E_DIM + lane), acc);
        }
        atomicAdd(&g_h1[n * E_DIM + lane], v * acc);
    }
}

__global__ void relu_bias_kernel(const float* __restrict__ bias1) {
    int idx = blockIdx.x * blockDim.x + threadIdx.x;
    if (idx < N_NODES * E_DIM) {
        float val = g_h1[idx] + bias1[idx & (E_DIM - 1)];
        g_h1[idx] = val > 0.f ? val : 0.f;
    }
}

__global__ void init_out_kernel(float* __restrict__ out,
                                const float* __restrict__ bias2) {
    int idx = blockIdx.x * blockDim.x + threadIdx.x;
    if (idx < N_NODES * C_DIM) out[idx] = bias2[idx & (C_DIM - 1)];
}

// ---------------------------------------------------------------------------
// Layer 2 fused edge kernel: one warp handles TWO edges (C=16 outputs each).
// Lanes 0..15 -> edge e0, lanes 16..31 -> edge e1.
// out[n,c] += v * sum_h h1[m,h] * w2[r,h,c]
// ---------------------------------------------------------------------------
__global__ void layer2_kernel(const int* __restrict__ rows,
                              const int* __restrict__ cols,
                              const float* __restrict__ vals,
                              float* __restrict__ out,
                              int nnz) {
    const int lane   = threadIdx.x & 31;
    const int warp   = (blockIdx.x * blockDim.x + threadIdx.x) >> 5;
    const int nwarps = (gridDim.x * blockDim.x) >> 5;
    const int half   = lane >> 4;
    const int c      = lane & 15;
    const int npairs = (nnz + 1) >> 1;
    for (int p = warp; p < npairs; p += nwarps) {
        int e0 = 2 * p;
        int e1 = 2 * p + 1;
        bool v1ok = (e1 < nnz);

        unsigned row0 = (unsigned)rows[e0];
        unsigned m0   = (unsigned)cols[e0];
        float    v0   = vals[e0];
        unsigned row1 = v1ok ? (unsigned)rows[e1] : 0u;
        unsigned m1   = v1ok ? (unsigned)cols[e1] : 0u;
        float    v1   = v1ok ? vals[e1] : 0.f;

        unsigned r0 = row0 / N_NODES, n0 = row0 - r0 * N_NODES;
        unsigned r1 = row1 / N_NODES, n1 = row1 - r1 * N_NODES;

        float h0 = g_h1[m0 * E_DIM + lane];
        float h1v = g_h1[m1 * E_DIM + lane];

        const float* w = g_w2 + (half ? r1 : r0) * (E_DIM * C_DIM);
        float acc = 0.f;
#pragma unroll
        for (int f = 0; f < E_DIM; f++) {
            float a  = __shfl_sync(0xffffffffu, h0, f);
            float b  = __shfl_sync(0xffffffffu, h1v, f);
            float hf = half ? b : a;
            acc = fmaf(hf, __ldg(w + f * C_DIM + c), acc);
        }
        float    vv = half ? v1 : v0;
        unsigned nn = half ? n1 : n0;
        atomicAdd(out + nn * C_DIM + c, vv * acc);   // v1==0 on tail -> adds 0
    }
}

// ---------------------------------------------------------------------------
extern "C" void kernel_launch(void* const* d_in, const int* in_sizes, int n_in,
                              void* d_out, int out_size) {
    const float* features = (const float*)d_in[0];
    const float* vals     = (const float*)d_in[1];
    const float* comps1   = (const float*)d_in[2];
    const float* bases1   = (const float*)d_in[3];
    const float* bias1    = (const float*)d_in[4];
    const float* comps2   = (const float*)d_in[5];
    const float* bases2   = (const float*)d_in[6];
    const float* bias2    = (const float*)d_in[7];
    const int*   rows     = (const int*)d_in[8];
    const int*   cols     = (const int*)d_in[9];
    float*       out      = (float*)d_out;
    const int    nnz      = in_sizes[8];

    // 1. build per-relation weights  (52224 threads dominate)
    compute_w_kernel<<<(R_REL * F_DIM * E_DIM + 255) / 256, 256>>>(
        comps1, bases1, comps2, bases2);

    // 2. zero h1 accumulator
    init_h1_kernel<<<(N_NODES * E_DIM + 255) / 256, 256>>>();

    // 3. layer-1 fused edge pass
    layer1_kernel<<<4096, 256>>>(rows, cols, vals, features, nnz);

    // 4. bias + relu
    relu_bias_kernel<<<(N_NODES * E_DIM + 255) / 256, 256>>>(bias1);

    // 5. init output with bias2
    init_out_kernel<<<(N_NODES * C_DIM + 255) / 256, 256>>>(out, bias2);

    // 6. layer-2 fused edge pass
    layer2_kernel<<<4096, 256>>>(rows, cols, vals, out, nnz);
}

// round 6
// speedup vs baseline: 2.2181x; 2.2181x over previous
#include <cuda_runtime.h>

#define N_NODES 50000
#define R_REL 51
#define F_DIM 32
#define E_DIM 32
#define C_DIM 16
#define B_BASES 30
#define NNZ_MAX 2001024

typedef unsigned long long ull;

// ---- scratch (__device__ globals: no allocation allowed) -------------------
__device__ float g_w1[R_REL * F_DIM * E_DIM];            // [r][f][e]  208 KB
__device__ float g_w2[R_REL * E_DIM * C_DIM];            // [r][h][c]  104 KB
__device__ __align__(16) float g_h1[N_NODES * E_DIM];    // 6.4 MB
__device__ unsigned g_hist[R_REL];
__device__ unsigned g_cursor[R_REL];
__device__ unsigned g_nm[NNZ_MAX];                       // (n<<16)|m (both <65536)
__device__ float    g_v[NNZ_MAX];
__device__ unsigned char g_r[NNZ_MAX];

// ---- packed f32x2 helpers --------------------------------------------------
__device__ __forceinline__ ull pack2(float lo, float hi) {
    ull r; asm("mov.b64 %0,{%1,%2};" : "=l"(r) : "f"(lo), "f"(hi)); return r;
}
__device__ __forceinline__ void unpack2(ull v, float& lo, float& hi) {
    asm("mov.b64 {%0,%1},%2;" : "=f"(lo), "=f"(hi) : "l"(v));
}
__device__ __forceinline__ ull ffma2(ull a, ull b, ull c) {
    ull d; asm("fma.rn.f32x2 %0,%1,%2,%3;" : "=l"(d) : "l"(a), "l"(b), "l"(c)); return d;
}
__device__ __forceinline__ ull fmul2(ull a, ull b) {
    ull d; asm("mul.rn.f32x2 %0,%1,%2;" : "=l"(d) : "l"(a), "l"(b)); return d;
}
__device__ __forceinline__ void red_add_v4(float* p, float a, float b, float c, float d) {
    asm volatile("red.global.add.v4.f32 [%0], {%1,%2,%3,%4};"
                 :: "l"(p), "f"(a), "f"(b), "f"(c), "f"(d) : "memory");
}

// ---------------------------------------------------------------------------
// Per-relation weights: w[r] = sum_b comps[r,b] * bases[b]
// ---------------------------------------------------------------------------
__global__ void compute_w_kernel(const float* __restrict__ comps1,
                                 const float* __restrict__ bases1,
                                 const float* __restrict__ comps2,
                                 const float* __restrict__ bases2) {
    int idx = blockIdx.x * blockDim.x + threadIdx.x;
    const int total1 = R_REL * F_DIM * E_DIM;
    const int total2 = R_REL * E_DIM * C_DIM;
    if (idx < total1) {
        int r = idx / (F_DIM * E_DIM);
        int fe = idx - r * (F_DIM * E_DIM);
        float acc = 0.f;
#pragma unroll
        for (int b = 0; b < B_BASES; b++)
            acc = fmaf(comps1[r * B_BASES + b], bases1[b * (F_DIM * E_DIM) + fe], acc);
        g_w1[idx] = acc;
    }
    if (idx < total2) {
        int r = idx / (E_DIM * C_DIM);
        int hc = idx - r * (E_DIM * C_DIM);
        float acc = 0.f;
#pragma unroll
        for (int b = 0; b < B_BASES; b++)
            acc = fmaf(comps2[r * B_BASES + b], bases2[b * (E_DIM * C_DIM) + hc], acc);
        g_w2[idx] = acc;
    }
}

// ---- relation bucketing ----------------------------------------------------
__global__ void zero_hist_kernel() {
    if (threadIdx.x < R_REL) { g_hist[threadIdx.x] = 0; g_cursor[threadIdx.x] = 0; }
}

__global__ void hist_kernel(const int* __restrict__ rows, int nnz) {
    __shared__ unsigned sh[R_REL];
    if (threadIdx.x < R_REL) sh[threadIdx.x] = 0;
    __syncthreads();
    for (int e = blockIdx.x * blockDim.x + threadIdx.x; e < nnz;
         e += gridDim.x * blockDim.x) {
        unsigned r = (unsigned)rows[e] / N_NODES;
        atomicAdd(&sh[r], 1u);
    }
    __syncthreads();
    if (threadIdx.x < R_REL) atomicAdd(&g_hist[threadIdx.x], sh[threadIdx.x]);
}

__global__ void scan_kernel() {
    if (threadIdx.x == 0) {
        unsigned s = 0;
        for (int r = 0; r < R_REL; r++) { g_cursor[r] = s; s += g_hist[r]; }
    }
}

// Block-aggregated scatter: 2 smem passes + one global atomic per (block, rel).
#define SCATTER_CHUNK 8192
__global__ void scatter_kernel(const int* __restrict__ rows,
                               const int* __restrict__ cols,
                               const float* __restrict__ vals, int nnz) {
    __shared__ unsigned cnt[R_REL];
    __shared__ unsigned base[R_REL];
    int start = blockIdx.x * SCATTER_CHUNK;
    if (start >= nnz) return;
    int end = min(start + SCATTER_CHUNK, nnz);

    if (threadIdx.x < R_REL) cnt[threadIdx.x] = 0;
    __syncthreads();
    for (int e = start + threadIdx.x; e < end; e += blockDim.x) {
        unsigned r = (unsigned)rows[e] / N_NODES;
        atomicAdd(&cnt[r], 1u);
    }
    __syncthreads();
    if (threadIdx.x < R_REL) {
        base[threadIdx.x] = atomicAdd(&g_cursor[threadIdx.x], cnt[threadIdx.x]);
        cnt[threadIdx.x] = 0;
    }
    __syncthreads();
    for (int e = start + threadIdx.x; e < end; e += blockDim.x) {
        unsigned row = (unsigned)rows[e];
        unsigned r = row / N_NODES;
        unsigned n = row - r * N_NODES;
        unsigned pos = base[r] + atomicAdd(&cnt[r], 1u);
        g_nm[pos] = (n << 16) | (unsigned)cols[e];
        g_v[pos]  = vals[e];
        g_r[pos]  = (unsigned char)r;
    }
}

// ---- small elementwise kernels --------------------------------------------
__global__ void init_h1_kernel() {
    int idx = blockIdx.x * blockDim.x + threadIdx.x;
    if (idx < N_NODES * E_DIM) g_h1[idx] = 0.f;
}
__global__ void relu_bias_kernel(const float* __restrict__ bias1) {
    int idx = blockIdx.x * blockDim.x + threadIdx.x;
    if (idx < N_NODES * E_DIM) {
        float v = g_h1[idx] + bias1[idx & (E_DIM - 1)];
        g_h1[idx] = v > 0.f ? v : 0.f;
    }
}
__global__ void init_out_kernel(float* __restrict__ out,
                                const float* __restrict__ bias2) {
    int idx = blockIdx.x * blockDim.x + threadIdx.x;
    if (idx < N_NODES * C_DIM) out[idx] = bias2[idx & (C_DIM - 1)];
}

// ---------------------------------------------------------------------------
// Layer 1: lane = edge (edges sorted by relation -> broadcast LDS of weights).
// w1 row = 32 floats = 8 ulonglong2.  acc[k] holds outputs e = (2k, 2k+1).
// ---------------------------------------------------------------------------
__global__ __launch_bounds__(512, 1)
void layer1_kernel(const float* __restrict__ x, int nnz) {
    extern __shared__ float sw[];                       // 52224 floats
    for (int i = threadIdx.x; i < R_REL * F_DIM * E_DIM; i += blockDim.x)
        sw[i] = g_w1[i];
    __syncthreads();

    const int lane = threadIdx.x & 31;
    int gw = (blockIdx.x * blockDim.x + threadIdx.x) >> 5;
    int nw = (gridDim.x * blockDim.x) >> 5;
    int ngroups = (nnz + 31) >> 5;

    for (int g = gw; g < ngroups; g += nw) {
        int idx = g * 32 + lane;
        int ce = idx < nnz ? idx : nnz - 1;
        unsigned nm = g_nm[ce];
        float v = idx < nnz ? g_v[ce] : 0.f;
        unsigned r = g_r[ce];
        unsigned n = nm >> 16;
        unsigned m = nm & 0xFFFFu;

        const float4* xr = (const float4*)(x + (size_t)m * F_DIM);
        const ulonglong2* wr = (const ulonglong2*)(sw + r * (F_DIM * E_DIM));

        ull acc[16];
#pragma unroll
        for (int i = 0; i < 16; i++) acc[i] = 0ull;

#pragma unroll
        for (int h = 0; h < 2; h++) {
            float4 xa0 = xr[h * 4 + 0];
            float4 xa1 = xr[h * 4 + 1];
            float4 xa2 = xr[h * 4 + 2];
            float4 xa3 = xr[h * 4 + 3];
            float xs[16] = { xa0.x, xa0.y, xa0.z, xa0.w,
                             xa1.x, xa1.y, xa1.z, xa1.w,
                             xa2.x, xa2.y, xa2.z, xa2.w,
                             xa3.x, xa3.y, xa3.z, xa3.w };
#pragma unroll
            for (int f = 0; f < 16; f++) {
                ull xp = pack2(xs[f], xs[f]);
                // row stride = 8 ulonglong2 (32 floats)
                const ulonglong2* wf = wr + (h * 16 + f) * 8;
#pragma unroll
                for (int j = 0; j < 8; j++) {
                    ulonglong2 q = wf[j];            // floats 4j .. 4j+3 (broadcast LDS.128)
                    acc[2 * j]     = ffma2(xp, q.x, acc[2 * j]);       // e = 4j, 4j+1
                    acc[2 * j + 1] = ffma2(xp, q.y, acc[2 * j + 1]);   // e = 4j+2, 4j+3
                }
            }
        }

        ull vp = pack2(v, v);
        float* hp = g_h1 + (size_t)n * E_DIM;
#pragma unroll
        for (int j = 0; j < 4; j++) {
            float a0, a1, a2, a3;
            unpack2(fmul2(acc[4 * j],     vp), a0, a1);
            unpack2(fmul2(acc[4 * j + 1], vp), a2, a3);
            red_add_v4(hp + 8 * j, a0, a1, a2, a3);          // e = 8j .. 8j+3
            float b0, b1, b2, b3;
            unpack2(fmul2(acc[4 * j + 2], vp), b0, b1);
            unpack2(fmul2(acc[4 * j + 3], vp), b2, b3);
            red_add_v4(hp + 8 * j + 4, b0, b1, b2, b3);      // e = 8j+4 .. 8j+7
        }
    }
}

// ---------------------------------------------------------------------------
// Layer 2: lane = edge.  w2 row = 16 floats = 4 ulonglong2.
// acc[k] holds outputs c = (2k, 2k+1), k = 0..7.
// ---------------------------------------------------------------------------
__global__ __launch_bounds__(512, 1)
void layer2_kernel(float* __restrict__ out, int nnz) {
    extern __shared__ float sw[];                       // 26112 floats
    for (int i = threadIdx.x; i < R_REL * E_DIM * C_DIM; i += blockDim.x)
        sw[i] = g_w2[i];
    __syncthreads();

    const int lane = threadIdx.x & 31;
    int gw = (blockIdx.x * blockDim.x + threadIdx.x) >> 5;
    int nw = (gridDim.x * blockDim.x) >> 5;
    int ngroups = (nnz + 31) >> 5;

    for (int g = gw; g < ngroups; g += nw) {
        int idx = g * 32 + lane;
        int ce = idx < nnz ? idx : nnz - 1;
        unsigned nm = g_nm[ce];
        float v = idx < nnz ? g_v[ce] : 0.f;
        unsigned r = g_r[ce];
        unsigned n = nm >> 16;
        unsigned m = nm & 0xFFFFu;

        const float4* hr = (const float4*)(g_h1 + (size_t)m * E_DIM);
        const ulonglong2* wr = (const ulonglong2*)(sw + r * (E_DIM * C_DIM));

        ull acc[8];
#pragma unroll
        for (int i = 0; i < 8; i++) acc[i] = 0ull;

#pragma unroll
        for (int h = 0; h < 2; h++) {
            float4 ha0 = hr[h * 4 + 0];
            float4 ha1 = hr[h * 4 + 1];
            float4 ha2 = hr[h * 4 + 2];
            float4 ha3 = hr[h * 4 + 3];
            float hs[16] = { ha0.x, ha0.y, ha0.z, ha0.w,
                             ha1.x, ha1.y, ha1.z, ha1.w,
                             ha2.x, ha2.y, ha2.z, ha2.w,
                             ha3.x, ha3.y, ha3.z, ha3.w };
#pragma unroll
            for (int f = 0; f < 16; f++) {
                ull xp = pack2(hs[f], hs[f]);
                // row stride = 4 ulonglong2 (16 floats)
                const ulonglong2* wf = wr + (h * 16 + f) * 4;
#pragma unroll
                for (int j = 0; j < 4; j++) {
                    ulonglong2 q = wf[j];            // floats 4j .. 4j+3
                    acc[2 * j]     = ffma2(xp, q.x, acc[2 * j]);       // c = 4j, 4j+1
                    acc[2 * j + 1] = ffma2(xp, q.y, acc[2 * j + 1]);   // c = 4j+2, 4j+3
                }
            }
        }

        ull vp = pack2(v, v);
        float* op = out + (size_t)n * C_DIM;
#pragma unroll
        for (int j = 0; j < 2; j++) {
            float a0, a1, a2, a3;
            unpack2(fmul2(acc[4 * j],     vp), a0, a1);
            unpack2(fmul2(acc[4 * j + 1], vp), a2, a3);
            red_add_v4(op + 8 * j, a0, a1, a2, a3);          // c = 8j .. 8j+3
            float b0, b1, b2, b3;
            unpack2(fmul2(acc[4 * j + 2], vp), b0, b1);
            unpack2(fmul2(acc[4 * j + 3], vp), b2, b3);
            red_add_v4(op + 8 * j + 4, b0, b1, b2, b3);      // c = 8j+4 .. 8j+7
        }
    }
}

// ---------------------------------------------------------------------------
extern "C" void kernel_launch(void* const* d_in, const int* in_sizes, int n_in,
                              void* d_out, int out_size) {
    const float* features = (const float*)d_in[0];
    const float* vals     = (const float*)d_in[1];
    const float* comps1   = (const float*)d_in[2];
    const float* bases1   = (const float*)d_in[3];
    const float* bias1    = (const float*)d_in[4];
    const float* comps2   = (const float*)d_in[5];
    const float* bases2   = (const float*)d_in[6];
    const float* bias2    = (const float*)d_in[7];
    const int*   rows     = (const int*)d_in[8];
    const int*   cols     = (const int*)d_in[9];
    float*       out      = (float*)d_out;
    const int    nnz      = in_sizes[8];

    const int smem1 = R_REL * F_DIM * E_DIM * (int)sizeof(float);  // 208896
    const int smem2 = R_REL * E_DIM * C_DIM * (int)sizeof(float);  // 104448
    static int attr_done = 0;
    if (!attr_done) {
        cudaFuncSetAttribute(layer1_kernel,
                             cudaFuncAttributeMaxDynamicSharedMemorySize, smem1);
        cudaFuncSetAttribute(layer2_kernel,
                             cudaFuncAttributeMaxDynamicSharedMemorySize, smem2);
        attr_done = 1;
    }

    // weights + bucketing (bucketing result reused by both layers)
    compute_w_kernel<<<(R_REL * F_DIM * E_DIM + 255) / 256, 256>>>(
        comps1, bases1, comps2, bases2);
    zero_hist_kernel<<<1, 64>>>();
    hist_kernel<<<512, 256>>>(rows, nnz);
    scan_kernel<<<1, 32>>>();
    scatter_kernel<<<(nnz + SCATTER_CHUNK - 1) / SCATTER_CHUNK, 512>>>(
        rows, cols, vals, nnz);

    init_h1_kernel<<<(N_NODES * E_DIM + 255) / 256, 256>>>();
    layer1_kernel<<<148, 512, smem1>>>(features, nnz);
    relu_bias_kernel<<<(N_NODES * E_DIM + 255) / 256, 256>>>(bias1);
    init_out_kernel<<<(N_NODES * C_DIM + 255) / 256, 256>>>(out, bias2);
    layer2_kernel<<<148, 512, smem2>>>(out, nnz);
}